// round 16
// baseline (speedup 1.0000x reference)
#include <cuda_runtime.h>
#include <math.h>

#define NUM_BODY 30
#define NPRED    32
#define NFORM    2
#define KTOP     3
#define SIGMA    0.1f
#define TEMP     0.07f
#define TOL      0.02f

__device__ __forceinline__ float case_rrf(float xa, float x3) {
    float ea = __expf(xa * (1.0f / TEMP));
    float e3 = __expf(x3 * (1.0f / TEMP));
    return __fdividef(fmaf(ea, xa, e3 * x3), ea + 2.0f + e3);
}

__global__ __launch_bounds__(32)
void logic_model_kernel(const float* __restrict__ t,        // (B,1)
                        const float* __restrict__ ds,       // (B,30)
                        const float* __restrict__ pi,       // (3,)
                        const float* __restrict__ A,        // (2,32)
                        const float* __restrict__ base_p,   // (1,)
                        const float* __restrict__ fw,       // (2,)
                        const float* __restrict__ prob,     // (4,)
                        float* __restrict__ out,            // (B,3)
                        int n, int rowblks)
{
    const int lane = threadIdx.x;
    const int f    = (blockIdx.x >= rowblks) ? 1 : 0;   // same-formula CTAs contiguous
    const int rb   = blockIdx.x - f * rowblks;
    const int b    = rb * 32 + lane;
    const int bc   = min(b, n - 1);
    const bool act = (b < n);

    // ---- issue ALL global loads up front (max MLP, single latency exposure) ----
    const float tb = t[bc];
    float dsl[NUM_BODY];
    {
        const float2* ds2 = (const float2*)(ds + bc * NUM_BODY);
        #pragma unroll
        for (int j = 0; j < NUM_BODY / 2; ++j) {
            float2 v = ds2[j];
            dsl[2 * j]     = v.x;
            dsl[2 * j + 1] = v.y;
        }
    }
    float av[NPRED];
    {
        const float4* A4 = (const float4*)(A + f * NPRED);
        #pragma unroll
        for (int q = 0; q < NPRED / 4; ++q) {
            float4 v = A4[q];
            av[4 * q]     = v.x;
            av[4 * q + 1] = v.y;
            av[4 * q + 2] = v.z;
            av[4 * q + 3] = v.w;
        }
    }
    const float base = base_p[0];
    const float p0 = prob[0], p1 = prob[1], p2 = prob[2], p3 = prob[3];
    const float fwf  = fw[f];
    const float lpif = __logf(pi[1 + f]);

    if (f == 0 && act) out[b * 3 + 0] = __logf(base) - tb * base + __logf(pi[0]);

    // ---- 4-case rrf / weight table (independent MUFU work, overlaps loads) ----
    float rrfT[4], wT[4];
    rrfT[0] = case_rrf(p0, (1.0f - p0) * p3);
    rrfT[1] = case_rrf(p1, (1.0f - p1) * p3);
    rrfT[2] = case_rrf(p2, (1.0f - p2) * p3);
    rrfT[3] = case_rrf(0.0f, p3);
    #pragma unroll
    for (int cs = 0; cs < 4; ++cs) wT[cs] = __expf(-rrfT[cs] * (1.0f / TEMP));

    // ---- top-3 via rank-by-comparison + single ballot ----
    // ballot bits come out ascending => matches jax top_k (desc value,
    // low-index tie-break) followed by jnp.sort
    int s0, s1, s2;
    {
        const float mine = av[lane];
        int rank = 0;
        #pragma unroll
        for (int k = 0; k < NPRED; ++k) {
            float vk = av[k];
            rank += (vk > mine || (vk == mine && k < lane)) ? 1 : 0;
        }
        unsigned m = __ballot_sync(0xffffffffu, rank < KTOP);
        s0 = __ffs(m) - 1;  m &= m - 1;
        s1 = __ffs(m) - 1;  m &= m - 1;
        s2 = __ffs(m) - 1;
    }
    // ascending: s0<s1<s2. pair (s0,s1) valid iff s1<30; pairs with s2 iff s2<30.
    const float pvA = (s1 < NUM_BODY) ? 1.0f : 0.0f;
    const float pvB = (s2 < NUM_BODY) ? 1.0f : 0.0f;
    const int c0i = s0;
    const int c1i = min(s1, NUM_BODY - 1);
    const int c2i = min(s2, NUM_BODY - 1);

    // ---- formula body: 4-way partial dot + fmax tree ----
    float dotP[4] = {av[NUM_BODY], av[NUM_BODY + 1], 0.0f, 0.0f};
    float mbtP[4] = {0.0f, 0.0f, 0.0f, 0.0f};
    #pragma unroll
    for (int j = 0; j < NUM_BODY; ++j) {
        float dv  = dsl[j];
        float aij = av[j];
        int q = j & 3;
        if (dv <= tb) {
            dotP[q] += aij;
            mbtP[q] = fmaxf(mbtP[q], dv * aij);
        }
    }
    float dot = (dotP[0] + dotP[1]) + (dotP[2] + dotP[3]);
    float mbt = fmaxf(fmaxf(mbtP[0], mbtP[1]), fmaxf(mbtP[2], mbtP[3]));

    float feat = __expf(-fabsf(dot - (float)KTOP) * (1.0f / SIGMA));

    const int   pcs[3] = {c0i, c0i, c1i};
    const int   qcs[3] = {c1i, c2i, c2i};
    const float pvs[3] = {pvA, pvB, pvB};
    float wsum = 0.0f, wxsum = 0.0f;
    #pragma unroll
    for (int p = 0; p < 3; ++p) {
        // L1-hit scalar loads (lines resident from the vectorized row load)
        float td = ds[bc * NUM_BODY + pcs[p]] - ds[bc * NUM_BODY + qcs[p]];
        int cs = 3;
        if (td > TOL) cs = 0;
        else if (fabsf(td) < TOL) cs = 1;
        else if (td < -TOL) cs = 2;
        float w = pvs[p] * wT[cs];
        wsum  += w;
        wxsum += w * rrfT[cs];
    }
    float col = __fdividef(wxsum, fmaxf(wsum, 1e-30f));
    if (pvA + pvB == 0.0f) col = 1.0f;
    feat *= col;

    float sg  = __fdividef(1.0f, 1.0f + __expf(-(tb - mbt)));
    float cur = fmaf(sg * feat, fwf, base);
    float lps = __logf(cur) + (-tb * cur + sg * (-mbt * base + mbt * cur)) + lpif;
    if (act) out[b * 3 + 1 + f] = lps;
}

extern "C" void kernel_launch(void* const* d_in, const int* in_sizes, int n_in,
                              void* d_out, int out_size)
{
    const float* t    = (const float*)d_in[0];
    const float* ds   = (const float*)d_in[1];
    const float* pi   = (const float*)d_in[2];
    const float* A    = (const float*)d_in[3];
    const float* base = (const float*)d_in[4];
    const float* fw   = (const float*)d_in[5];
    const float* prob = (const float*)d_in[6];
    float* out = (float*)d_out;

    const int n = in_sizes[0];
    const int rowblks = (n + 31) / 32;
    const int blocks  = rowblks * NFORM;      // 32 CTAs x 32 threads, one wave
    logic_model_kernel<<<blocks, 32>>>(t, ds, pi, A, base, fw, prob, out, n, rowblks);
}

// round 17
// speedup vs baseline: 1.1082x; 1.1082x over previous
#include <cuda_runtime.h>
#include <math.h>

#define NUM_BODY 30
#define NPRED    32
#define NFORM    2
#define KTOP     3
#define SIGMA    0.1f
#define TEMP     0.07f
#define TOL      0.02f

__device__ __forceinline__ float case_rrf(float xa, float x3) {
    float ea = __expf(xa * (1.0f / TEMP));
    float e3 = __expf(x3 * (1.0f / TEMP));
    return __fdividef(fmaf(ea, xa, e3 * x3), ea + 2.0f + e3);
}

__global__ __launch_bounds__(32)
void logic_model_kernel(const float* __restrict__ t,        // (B,1)
                        const float* __restrict__ ds,       // (B,30)
                        const float* __restrict__ pi,       // (3,)
                        const float* __restrict__ A,        // (2,32)
                        const float* __restrict__ base_p,   // (1,)
                        const float* __restrict__ fw,       // (2,)
                        const float* __restrict__ prob,     // (4,)
                        float* __restrict__ out,            // (B,3)
                        int n, int rowblks)
{
    const int lane = threadIdx.x;
    const int f    = (blockIdx.x >= rowblks) ? 1 : 0;   // same-formula CTAs contiguous
    const int rb   = blockIdx.x - f * rowblks;
    const int b    = rb * 32 + lane;
    const int bc   = min(b, n - 1);
    const bool act = (b < n);

    // ---- issue ALL global loads up front (max MLP, single latency exposure) ----
    const float tb = t[bc];
    float dsl[NUM_BODY];
    {
        const float2* ds2 = (const float2*)(ds + bc * NUM_BODY);
        #pragma unroll
        for (int j = 0; j < NUM_BODY / 2; ++j) {
            float2 v = ds2[j];
            dsl[2 * j]     = v.x;
            dsl[2 * j + 1] = v.y;
        }
    }
    float av[NPRED];
    {
        const float4* A4 = (const float4*)(A + f * NPRED);
        #pragma unroll
        for (int q = 0; q < NPRED / 4; ++q) {
            float4 v = A4[q];
            av[4 * q]     = v.x;
            av[4 * q + 1] = v.y;
            av[4 * q + 2] = v.z;
            av[4 * q + 3] = v.w;
        }
    }
    const float base = base_p[0];
    const float p0 = prob[0], p1 = prob[1], p2 = prob[2], p3 = prob[3];
    const float fwf  = fw[f];
    const float lpif = __logf(pi[1 + f]);

    if (f == 0 && act) out[b * 3 + 0] = __logf(base) - tb * base + __logf(pi[0]);

    // ---- 4-case rrf / weight table (independent MUFU work, overlaps loads) ----
    float rrfT[4], wT[4];
    rrfT[0] = case_rrf(p0, (1.0f - p0) * p3);
    rrfT[1] = case_rrf(p1, (1.0f - p1) * p3);
    rrfT[2] = case_rrf(p2, (1.0f - p2) * p3);
    rrfT[3] = case_rrf(0.0f, p3);
    #pragma unroll
    for (int cs = 0; cs < 4; ++cs) wT[cs] = __expf(-rrfT[cs] * (1.0f / TEMP));

    // ---- top-3 via rank-by-comparison + single ballot ----
    // ballot bits come out ascending => matches jax top_k (desc value,
    // low-index tie-break) followed by jnp.sort
    int s0, s1, s2;
    {
        const float mine = av[lane];
        int rank = 0;
        #pragma unroll
        for (int k = 0; k < NPRED; ++k) {
            float vk = av[k];
            rank += (vk > mine || (vk == mine && k < lane)) ? 1 : 0;
        }
        unsigned m = __ballot_sync(0xffffffffu, rank < KTOP);
        s0 = __ffs(m) - 1;  m &= m - 1;
        s1 = __ffs(m) - 1;  m &= m - 1;
        s2 = __ffs(m) - 1;
    }
    // ascending: s0<s1<s2. pair (s0,s1) valid iff s1<30; pairs with s2 iff s2<30.
    const float pvA = (s1 < NUM_BODY) ? 1.0f : 0.0f;
    const float pvB = (s2 < NUM_BODY) ? 1.0f : 0.0f;
    const int c0i = s0;
    const int c1i = min(s1, NUM_BODY - 1);
    const int c2i = min(s2, NUM_BODY - 1);

    // ---- formula body: 4-way partial dot + fmax tree ----
    float dotP[4] = {av[NUM_BODY], av[NUM_BODY + 1], 0.0f, 0.0f};
    float mbtP[4] = {0.0f, 0.0f, 0.0f, 0.0f};
    #pragma unroll
    for (int j = 0; j < NUM_BODY; ++j) {
        float dv  = dsl[j];
        float aij = av[j];
        int q = j & 3;
        if (dv <= tb) {
            dotP[q] += aij;
            mbtP[q] = fmaxf(mbtP[q], dv * aij);
        }
    }
    float dot = (dotP[0] + dotP[1]) + (dotP[2] + dotP[3]);
    float mbt = fmaxf(fmaxf(mbtP[0], mbtP[1]), fmaxf(mbtP[2], mbtP[3]));

    float feat = __expf(-fabsf(dot - (float)KTOP) * (1.0f / SIGMA));

    const int   pcs[3] = {c0i, c0i, c1i};
    const int   qcs[3] = {c1i, c2i, c2i};
    const float pvs[3] = {pvA, pvB, pvB};
    float wsum = 0.0f, wxsum = 0.0f;
    #pragma unroll
    for (int p = 0; p < 3; ++p) {
        // L1-hit scalar loads (lines resident from the vectorized row load)
        float td = ds[bc * NUM_BODY + pcs[p]] - ds[bc * NUM_BODY + qcs[p]];
        int cs = 3;
        if (td > TOL) cs = 0;
        else if (fabsf(td) < TOL) cs = 1;
        else if (td < -TOL) cs = 2;
        float w = pvs[p] * wT[cs];
        wsum  += w;
        wxsum += w * rrfT[cs];
    }
    float col = __fdividef(wxsum, fmaxf(wsum, 1e-30f));
    if (pvA + pvB == 0.0f) col = 1.0f;
    feat *= col;

    float sg  = __fdividef(1.0f, 1.0f + __expf(-(tb - mbt)));
    float cur = fmaf(sg * feat, fwf, base);
    float lps = __logf(cur) + (-tb * cur + sg * (-mbt * base + mbt * cur)) + lpif;
    if (act) out[b * 3 + 1 + f] = lps;
}

extern "C" void kernel_launch(void* const* d_in, const int* in_sizes, int n_in,
                              void* d_out, int out_size)
{
    const float* t    = (const float*)d_in[0];
    const float* ds   = (const float*)d_in[1];
    const float* pi   = (const float*)d_in[2];
    const float* A    = (const float*)d_in[3];
    const float* base = (const float*)d_in[4];
    const float* fw   = (const float*)d_in[5];
    const float* prob = (const float*)d_in[6];
    float* out = (float*)d_out;

    const int n = in_sizes[0];
    const int rowblks = (n + 31) / 32;
    const int blocks  = rowblks * NFORM;      // 32 CTAs x 32 threads, one wave
    logic_model_kernel<<<blocks, 32>>>(t, ds, pi, A, base, fw, prob, out, n, rowblks);
}